// round 13
// baseline (speedup 1.0000x reference)
#include <cuda_runtime.h>
#include <cuda_bf16.h>
#include <math.h>

// Problem constants
#define NTOK   8192
#define DIM    256
#define HH     8
#define HD     32
#define WW     64
#define NW     128          // NTOK / WW
#define T6     216          // 3*40 + 3*32
#define QSCALE 0.17677669529663687f   // 32^-0.5

typedef unsigned long long u64;

// ---- packed f32x2 helpers (sm_100+) ----
__device__ __forceinline__ void ffma2(u64 &c, u64 a, u64 b) {
    asm("fma.rn.f32x2 %0, %1, %2, %0;" : "+l"(c) : "l"(a), "l"(b));
}
__device__ __forceinline__ u64 pk2(float lo, float hi) {
    u64 r; asm("mov.b64 %0, {%1, %2};" : "=l"(r) : "f"(lo), "f"(hi)); return r;
}
__device__ __forceinline__ float2 up2(u64 v) {
    float2 r; asm("mov.b64 {%0, %1}, %2;" : "=f"(r.x), "=f"(r.y) : "l"(v)); return r;
}
__device__ __forceinline__ float hsum2(u64 v) { float2 p = up2(v); return p.x + p.y; }

// Global scratch (static device allocations -- allowed)
__device__ float g_q[NTOK * DIM];
__device__ float g_k[NTOK * DIM];
__device__ float g_v[NTOK * DIM];
__device__ float g_att[NTOK * DIM];

// ---------------------------------------------------------------------------
// QKV GEMM: BM=128 BN=128 BK=16, 256 threads, 8x8 via f32x2, double-buffered.
// (R7 version, measured 69.9us)
// ---------------------------------------------------------------------------
__global__ __launch_bounds__(256) void qkv_gemm_kernel(
    const float* __restrict__ A, const float* __restrict__ Wt,
    const float* __restrict__ bias)
{
    __shared__ __align__(16) float As[2][16][132];
    __shared__ __align__(16) float Bs[2][16][132];
    const int m0 = blockIdx.x * 128, n0 = blockIdx.y * 128;
    const int tid = threadIdx.x;
    const int tx = tid & 15, ty = tid >> 4;
    const int lr = tid >> 1, lc = (tid & 1) * 8;

    u64 c2[8][4];
#pragma unroll
    for (int i = 0; i < 8; i++)
#pragma unroll
        for (int j = 0; j < 4; j++) c2[i][j] = pk2(0.f, 0.f);

    const float* Arow = A  + (m0 + lr) * 256 + lc;
    const float* Brow = Wt + (n0 + lr) * 256 + lc;

    {
        float4 a0 = *(const float4*)(Arow);
        float4 a1 = *(const float4*)(Arow + 4);
        float4 b0 = *(const float4*)(Brow);
        float4 b1 = *(const float4*)(Brow + 4);
        As[0][lc + 0][lr] = a0.x; As[0][lc + 1][lr] = a0.y;
        As[0][lc + 2][lr] = a0.z; As[0][lc + 3][lr] = a0.w;
        As[0][lc + 4][lr] = a1.x; As[0][lc + 5][lr] = a1.y;
        As[0][lc + 6][lr] = a1.z; As[0][lc + 7][lr] = a1.w;
        Bs[0][lc + 0][lr] = b0.x; Bs[0][lc + 1][lr] = b0.y;
        Bs[0][lc + 2][lr] = b0.z; Bs[0][lc + 3][lr] = b0.w;
        Bs[0][lc + 4][lr] = b1.x; Bs[0][lc + 5][lr] = b1.y;
        Bs[0][lc + 6][lr] = b1.z; Bs[0][lc + 7][lr] = b1.w;
    }
    __syncthreads();

    for (int step = 0; step < 16; step++) {
        const int cur = step & 1, nxt = cur ^ 1;
        float4 na0, na1, nb0, nb1;
        if (step < 15) {
            const int kk = (step + 1) * 16;
            na0 = *(const float4*)(Arow + kk);
            na1 = *(const float4*)(Arow + kk + 4);
            nb0 = *(const float4*)(Brow + kk);
            nb1 = *(const float4*)(Brow + kk + 4);
        }
#pragma unroll
        for (int k = 0; k < 16; k++) {
            float4 av0 = *(const float4*)&As[cur][k][ty * 4];
            float4 av1 = *(const float4*)&As[cur][k][64 + ty * 4];
            ulonglong2 bl = *(const ulonglong2*)&Bs[cur][k][tx * 4];
            ulonglong2 bh = *(const ulonglong2*)&Bs[cur][k][64 + tx * 4];
            u64 bb[4] = {bl.x, bl.y, bh.x, bh.y};
            float aa[8] = {av0.x, av0.y, av0.z, av0.w,
                           av1.x, av1.y, av1.z, av1.w};
#pragma unroll
            for (int i = 0; i < 8; i++) {
                u64 ad = pk2(aa[i], aa[i]);
#pragma unroll
                for (int j = 0; j < 4; j++) ffma2(c2[i][j], ad, bb[j]);
            }
        }
        if (step < 15) {
            As[nxt][lc + 0][lr] = na0.x; As[nxt][lc + 1][lr] = na0.y;
            As[nxt][lc + 2][lr] = na0.z; As[nxt][lc + 3][lr] = na0.w;
            As[nxt][lc + 4][lr] = na1.x; As[nxt][lc + 5][lr] = na1.y;
            As[nxt][lc + 6][lr] = na1.z; As[nxt][lc + 7][lr] = na1.w;
            Bs[nxt][lc + 0][lr] = nb0.x; Bs[nxt][lc + 1][lr] = nb0.y;
            Bs[nxt][lc + 2][lr] = nb0.z; Bs[nxt][lc + 3][lr] = nb0.w;
            Bs[nxt][lc + 4][lr] = nb1.x; Bs[nxt][lc + 5][lr] = nb1.y;
            Bs[nxt][lc + 6][lr] = nb1.z; Bs[nxt][lc + 7][lr] = nb1.w;
            __syncthreads();
        }
    }

#pragma unroll
    for (int i = 0; i < 8; i++) {
        int m = m0 + ((i < 4) ? (ty * 4 + i) : (64 + ty * 4 + i - 4));
#pragma unroll
        for (int g = 0; g < 2; g++) {
            int n = n0 + g * 64 + tx * 4;
            float2 p0 = up2(c2[i][g * 2]);
            float2 p1 = up2(c2[i][g * 2 + 1]);
            float4 b4 = *(const float4*)&bias[n];
            float4 o;
            o.x = p0.x + b4.x; o.y = p0.y + b4.y;
            o.z = p1.x + b4.z; o.w = p1.y + b4.w;
            int s = n >> 8, col = n & 255;
            float* dst;
            if (s == 0) {
                o.x *= QSCALE; o.y *= QSCALE; o.z *= QSCALE; o.w *= QSCALE;
                dst = g_q;
            } else if (s == 1) dst = g_k;
            else               dst = g_v;
            *(float4*)&dst[m * 256 + col] = o;
        }
    }
}

// ---------------------------------------------------------------------------
// Projection GEMM, same structure (double-buffered)
// ---------------------------------------------------------------------------
__global__ __launch_bounds__(256) void proj_gemm_kernel(
    const float* __restrict__ Wt, const float* __restrict__ bias,
    float* __restrict__ out)
{
    __shared__ __align__(16) float As[2][16][132];
    __shared__ __align__(16) float Bs[2][16][132];
    const int m0 = blockIdx.x * 128, n0 = blockIdx.y * 128;
    const int tid = threadIdx.x;
    const int tx = tid & 15, ty = tid >> 4;
    const int lr = tid >> 1, lc = (tid & 1) * 8;

    u64 c2[8][4];
#pragma unroll
    for (int i = 0; i < 8; i++)
#pragma unroll
        for (int j = 0; j < 4; j++) c2[i][j] = pk2(0.f, 0.f);

    const float* Arow = g_att + (m0 + lr) * 256 + lc;
    const float* Brow = Wt    + (n0 + lr) * 256 + lc;

    {
        float4 a0 = *(const float4*)(Arow);
        float4 a1 = *(const float4*)(Arow + 4);
        float4 b0 = *(const float4*)(Brow);
        float4 b1 = *(const float4*)(Brow + 4);
        As[0][lc + 0][lr] = a0.x; As[0][lc + 1][lr] = a0.y;
        As[0][lc + 2][lr] = a0.z; As[0][lc + 3][lr] = a0.w;
        As[0][lc + 4][lr] = a1.x; As[0][lc + 5][lr] = a1.y;
        As[0][lc + 6][lr] = a1.z; As[0][lc + 7][lr] = a1.w;
        Bs[0][lc + 0][lr] = b0.x; Bs[0][lc + 1][lr] = b0.y;
        Bs[0][lc + 2][lr] = b0.z; Bs[0][lc + 3][lr] = b0.w;
        Bs[0][lc + 4][lr] = b1.x; Bs[0][lc + 5][lr] = b1.y;
        Bs[0][lc + 6][lr] = b1.z; Bs[0][lc + 7][lr] = b1.w;
    }
    __syncthreads();

    for (int step = 0; step < 16; step++) {
        const int cur = step & 1, nxt = cur ^ 1;
        float4 na0, na1, nb0, nb1;
        if (step < 15) {
            const int kk = (step + 1) * 16;
            na0 = *(const float4*)(Arow + kk);
            na1 = *(const float4*)(Arow + kk + 4);
            nb0 = *(const float4*)(Brow + kk);
            nb1 = *(const float4*)(Brow + kk + 4);
        }
#pragma unroll
        for (int k = 0; k < 16; k++) {
            float4 av0 = *(const float4*)&As[cur][k][ty * 4];
            float4 av1 = *(const float4*)&As[cur][k][64 + ty * 4];
            ulonglong2 bl = *(const ulonglong2*)&Bs[cur][k][tx * 4];
            ulonglong2 bh = *(const ulonglong2*)&Bs[cur][k][64 + tx * 4];
            u64 bb[4] = {bl.x, bl.y, bh.x, bh.y};
            float aa[8] = {av0.x, av0.y, av0.z, av0.w,
                           av1.x, av1.y, av1.z, av1.w};
#pragma unroll
            for (int i = 0; i < 8; i++) {
                u64 ad = pk2(aa[i], aa[i]);
#pragma unroll
                for (int j = 0; j < 4; j++) ffma2(c2[i][j], ad, bb[j]);
            }
        }
        if (step < 15) {
            As[nxt][lc + 0][lr] = na0.x; As[nxt][lc + 1][lr] = na0.y;
            As[nxt][lc + 2][lr] = na0.z; As[nxt][lc + 3][lr] = na0.w;
            As[nxt][lc + 4][lr] = na1.x; As[nxt][lc + 5][lr] = na1.y;
            As[nxt][lc + 6][lr] = na1.z; As[nxt][lc + 7][lr] = na1.w;
            Bs[nxt][lc + 0][lr] = nb0.x; Bs[nxt][lc + 1][lr] = nb0.y;
            Bs[nxt][lc + 2][lr] = nb0.z; Bs[nxt][lc + 3][lr] = nb0.w;
            Bs[nxt][lc + 4][lr] = nb1.x; Bs[nxt][lc + 5][lr] = nb1.y;
            Bs[nxt][lc + 6][lr] = nb1.z; Bs[nxt][lc + 7][lr] = nb1.w;
            __syncthreads();
        }
    }

#pragma unroll
    for (int i = 0; i < 8; i++) {
        int m = m0 + ((i < 4) ? (ty * 4 + i) : (64 + ty * 4 + i - 4));
#pragma unroll
        for (int g = 0; g < 2; g++) {
            int n = n0 + g * 64 + tx * 4;
            float2 p0 = up2(c2[i][g * 2]);
            float2 p1 = up2(c2[i][g * 2 + 1]);
            float4 b4 = *(const float4*)&bias[n];
            float4 o;
            o.x = p0.x + b4.x; o.y = p0.y + b4.y;
            o.z = p1.x + b4.z; o.w = p1.y + b4.w;
            *(float4*)&out[m * 256 + n] = o;
        }
    }
}

// ---------------------------------------------------------------------------
// Attention kernel: one block per (window, head). 768 threads (24 warps).
// Parallel phases (loads, Dq/Dk, zero/vtab, logits) use all 24 warps;
// softmax/binning/output stay on warps 0-15 (R7-validated structure).
// Shared layout identical to R7 (53024 floats = 212096 B).
// ---------------------------------------------------------------------------
#define SM_FLOATS 53024
#define SMEM_BYTES (SM_FLOATS * 4)

__global__ __launch_bounds__(768) void attn_kernel(
    const float* __restrict__ n_coords,
    const float* __restrict__ qx, const float* __restrict__ kx,
    const float* __restrict__ vx,
    const float* __restrict__ qr, const float* __restrict__ kr,
    const float* __restrict__ vr)
{
    extern __shared__ __align__(16) float sm[];
    float* scw   = sm;
    float* sq    = sm + 384;     // stride 33
    float* sk    = sm + 2496;    // stride 33
    float* svT   = sm + 4608;    // stride 65
    float* stabQ = sm + 6688;
    float* stabK = sm + 13600;
    float* sdq   = sm + 20512;   // stride 220
    float* sdk   = sm + 34592;   // stride 220
    float* slogT = sm + 48672;   // stride 68, [j][i]
    float* satT  = sm + 20512;   // stride 68, [t][i]   (aliases sdq after logits)
    float* vtabT = sm + 35200;   // stride 217, [d][t]  (aliases sdk tail)
    u64*   s_idx = (u64*)(sm + 6688);   // u64[4096] over stabQ/K (after Dq/Dk)

    const int nb = blockIdx.x, h = blockIdx.y;
    const int tid = threadIdx.x;
    const int l = tid & 31, w = tid >> 5;
    const int tok0 = nb * WW;

    // ---- load coords, q, k, v(T), both tables (24 warps) ----
    for (int s = tid; s < WW * 6; s += 768) {
        int i = s / 6, c = s % 6;
        scw[s] = n_coords[(tok0 + i) * 6 + c] * (c < 3 ? 4.0f : 8.0f);
    }
    for (int s = tid; s < WW * HD; s += 768) {
        int i = s >> 5, d = s & 31;
        int g = (tok0 + i) * 256 + h * 32 + d;
        sq[i * 33 + d]  = g_q[g];
        sk[i * 33 + d]  = g_k[g];
        svT[d * 65 + i] = g_v[g];
    }
    for (int s = tid; s < T6 * HD; s += 768) {
        int t = s >> 5, d = s & 31;
        stabQ[s] = (t < 120) ? qx[(t * 8 + h) * 32 + d]
                             : qr[((t - 120) * 8 + h) * 32 + d];
        stabK[s] = (t < 120) ? kx[(t * 8 + h) * 32 + d]
                             : kr[((t - 120) * 8 + h) * 32 + d];
    }
    __syncthreads();

    // ---- Dq / Dk : i = tid&63, 12 groups x 18 t ----
    {
        const int i = tid & 63, grp = tid >> 6;   // grp in [0,12)
        const int t0 = grp * 18, t1 = t0 + 18;
        u64 a2[16];
#pragma unroll
        for (int d2 = 0; d2 < 16; d2++)
            a2[d2] = pk2(sq[i * 33 + 2 * d2], sq[i * 33 + 2 * d2 + 1]);
        for (int t = t0; t < t1; t++) {
            const ulonglong2* tv = (const ulonglong2*)(stabQ + t * 32);
            u64 acc = pk2(0.f, 0.f);
#pragma unroll
            for (int d4 = 0; d4 < 8; d4++) {
                ulonglong2 tvv = tv[d4];
                ffma2(acc, a2[2 * d4],     tvv.x);
                ffma2(acc, a2[2 * d4 + 1], tvv.y);
            }
            sdq[i * 220 + t] = hsum2(acc);
        }
#pragma unroll
        for (int d2 = 0; d2 < 16; d2++)
            a2[d2] = pk2(sk[i * 33 + 2 * d2], sk[i * 33 + 2 * d2 + 1]);
        for (int t = t0; t < t1; t++) {
            const ulonglong2* tv = (const ulonglong2*)(stabK + t * 32);
            u64 acc = pk2(0.f, 0.f);
#pragma unroll
            for (int d4 = 0; d4 < 8; d4++) {
                ulonglong2 tvv = tv[d4];
                ffma2(acc, a2[2 * d4],     tvv.x);
                ffma2(acc, a2[2 * d4 + 1], tvv.y);
            }
            sdk[i * 220 + t] = hsum2(acc);
        }
    }
    __syncthreads();

    // ---- logits: flat (row,jj) tasks over 24 warps ----
    {
        const int basec[6] = {0, 40, 80, 120, 152, 184};
        const int offc[6]  = {20, 20, 20, 16, 16, 16};
        const int hic[6]   = {39, 39, 39, 31, 31, 31};
        for (int task = w; task < 128; task += 24) {
            int i = task & 63;
            int jj = task >> 6;
            int j = l + jj * 32;
            float ci[6];
#pragma unroll
            for (int c = 0; c < 6; c++) ci[c] = scw[i * 6 + c];
            u64 q2[16];
#pragma unroll
            for (int d2 = 0; d2 < 16; d2++)
                q2[d2] = pk2(sq[i * 33 + 2 * d2], sq[i * 33 + 2 * d2 + 1]);
            const float* krow = sk + j * 33;
            u64 acc2 = pk2(0.f, 0.f);
#pragma unroll
            for (int d2 = 0; d2 < 16; d2++)
                ffma2(acc2, q2[d2], pk2(krow[2 * d2], krow[2 * d2 + 1]));
            float acc = hsum2(acc2);
            u64 pack = 0;
#pragma unroll
            for (int c = 0; c < 6; c++) {
                int id = (int)floorf(ci[c] - scw[j * 6 + c]) + offc[c];
                id = min(max(id, 0), hic[c]);
                int t = basec[c] + id;
                acc += sdq[i * 220 + t] + sdk[j * 220 + t];
                pack |= (u64)t << (8 * c);
            }
            slogT[j * 68 + i] = acc;
            s_idx[i * 64 + j] = pack;
        }
    }
    __syncthreads();   // logits reads of sdq/sdk complete; satT/vtabT may alias

    // ---- zero satT bins, load v-table (24 warps) ----
    for (int s = tid; s < T6 * 68; s += 768) satT[s] = 0.f;
    for (int s = tid; s < T6 * HD; s += 768) {
        int t = s >> 5, d = s & 31;
        float val = (t < 120) ? vx[(t * 8 + h) * 32 + d]
                              : vr[((t - 120) * 8 + h) * 32 + d];
        vtabT[d * 217 + t] = val;
    }
    __syncthreads();

    // ---- softmax + binning + output: warps 0-15 (R7-exact) ----
    if (w < 16) {
#pragma unroll
        for (int r = 0; r < 4; r++) {
            int i = w * 4 + r;
            float v0 = slogT[l * 68 + i], v1 = slogT[(l + 32) * 68 + i];
            float m = fmaxf(v0, v1);
#pragma unroll
            for (int o = 16; o > 0; o >>= 1)
                m = fmaxf(m, __shfl_xor_sync(0xffffffffu, m, o));
            float e0 = __expf(v0 - m), e1 = __expf(v1 - m);
            float s = e0 + e1;
#pragma unroll
            for (int o = 16; o > 0; o >>= 1)
                s += __shfl_xor_sync(0xffffffffu, s, o);
            float inv = 1.0f / s;
            slogT[l * 68 + i]        = e0 * inv;
            slogT[(l + 32) * 68 + i] = e1 * inv;
        }
        __syncwarp();

        if (l < 24) {
            int r = l / 6, c = l % 6;
            int i = w * 4 + r;
            const u64* ip = s_idx + i * 64;
            const int sh = 8 * c;
            for (int j = 0; j < 64; j++) {
                int t = (int)((ip[j] >> sh) & 255u);
                satT[t * 68 + i] += slogT[j * 68 + i];
            }
        }
        __syncwarp();

        {
            const int i0 = w * 4;
            u64 acc01 = pk2(0.f, 0.f), acc23 = pk2(0.f, 0.f);
            const float* svrow = svT + l * 65;
#pragma unroll 8
            for (int j = 0; j < 64; j++) {
                float4 a4 = *(const float4*)&slogT[j * 68 + i0];
                float v = svrow[j];
                u64 vd = pk2(v, v);
                ffma2(acc01, pk2(a4.x, a4.y), vd);
                ffma2(acc23, pk2(a4.z, a4.w), vd);
            }
            const float* vtrow = vtabT + l * 217;
#pragma unroll 8
            for (int t = 0; t < T6; t++) {
                float4 a4 = *(const float4*)&satT[t * 68 + i0];
                float v = vtrow[t];
                u64 vd = pk2(v, v);
                ffma2(acc01, pk2(a4.x, a4.y), vd);
                ffma2(acc23, pk2(a4.z, a4.w), vd);
            }
            float2 o01 = up2(acc01), o23 = up2(acc23);
            const int ob = (tok0 + i0) * 256 + h * 32 + l;
            g_att[ob]       = o01.x;
            g_att[ob + 256] = o01.y;
            g_att[ob + 512] = o23.x;
            g_att[ob + 768] = o23.y;
        }
    }
}

// ---------------------------------------------------------------------------
extern "C" void kernel_launch(void* const* d_in, const int* in_sizes, int n_in,
                              void* d_out, int out_size)
{
    const float* feats    = (const float*)d_in[0];
    const float* n_coords = (const float*)d_in[1];
    const float* qkv_w    = (const float*)d_in[2];
    const float* qkv_b    = (const float*)d_in[3];
    const float* qx       = (const float*)d_in[4];
    const float* kx       = (const float*)d_in[5];
    const float* vx       = (const float*)d_in[6];
    const float* qr       = (const float*)d_in[7];
    const float* kr       = (const float*)d_in[8];
    const float* vr       = (const float*)d_in[9];
    const float* pw       = (const float*)d_in[10];
    const float* pb       = (const float*)d_in[11];
    float* out = (float*)d_out;

    cudaFuncSetAttribute(attn_kernel,
                         cudaFuncAttributeMaxDynamicSharedMemorySize,
                         SMEM_BYTES);

    qkv_gemm_kernel<<<dim3(64, 6), 256>>>(feats, qkv_w, qkv_b);
    attn_kernel<<<dim3(NW, HH), 768, SMEM_BYTES>>>(n_coords, qx, kx, vx,
                                                   qr, kr, vr);
    proj_gemm_kernel<<<dim3(64, 2), 256>>>(pw, pb, out);
}

// round 15
// speedup vs baseline: 1.1469x; 1.1469x over previous
#include <cuda_runtime.h>
#include <cuda_bf16.h>
#include <math.h>

// Problem constants
#define NTOK   8192
#define DIM    256
#define HH     8
#define HD     32
#define WW     64
#define NW     128          // NTOK / WW
#define T6     216          // 3*40 + 3*32
#define QSCALE 0.17677669529663687f   // 32^-0.5

typedef unsigned long long u64;
typedef unsigned int       u32;

// ---- packed f32x2 helpers (sm_100+) ----
__device__ __forceinline__ void ffma2(u64 &c, u64 a, u64 b) {
    asm("fma.rn.f32x2 %0, %1, %2, %0;" : "+l"(c) : "l"(a), "l"(b));
}
__device__ __forceinline__ u64 pk2(float lo, float hi) {
    u64 r; asm("mov.b64 %0, {%1, %2};" : "=l"(r) : "f"(lo), "f"(hi)); return r;
}
__device__ __forceinline__ float2 up2(u64 v) {
    float2 r; asm("mov.b64 {%0, %1}, %2;" : "=f"(r.x), "=f"(r.y) : "l"(v)); return r;
}
__device__ __forceinline__ float hsum2(u64 v) { float2 p = up2(v); return p.x + p.y; }

// Global scratch (static device allocations -- allowed)
__device__ float g_q[NTOK * DIM];
__device__ float g_k[NTOK * DIM];
__device__ float g_v[NTOK * DIM];
__device__ float g_att[NTOK * DIM];

// ---------------------------------------------------------------------------
// mma.sync helpers (sm_80+ baseline PTX; works on sm_103 non-a)
// ---------------------------------------------------------------------------
__device__ __forceinline__ u32 smem_u32(const void* p) {
    u32 a;
    asm("{ .reg .u64 t; cvta.to.shared.u64 t, %1; cvt.u32.u64 %0, t; }"
        : "=r"(a) : "l"(p));
    return a;
}
__device__ __forceinline__ void ldsm4(u32* r, u32 addr) {
    asm volatile("ldmatrix.sync.aligned.m8n8.x4.shared.b16 {%0,%1,%2,%3}, [%4];"
                 : "=r"(r[0]), "=r"(r[1]), "=r"(r[2]), "=r"(r[3]) : "r"(addr));
}
__device__ __forceinline__ void ldsm2(u32* r, u32 addr) {
    asm volatile("ldmatrix.sync.aligned.m8n8.x2.shared.b16 {%0,%1}, [%2];"
                 : "=r"(r[0]), "=r"(r[1]) : "r"(addr));
}
__device__ __forceinline__ void mma_bf16(float* d, const u32* a, const u32* b) {
    asm volatile(
        "mma.sync.aligned.m16n8k16.row.col.f32.bf16.bf16.f32 "
        "{%0,%1,%2,%3}, {%4,%5,%6,%7}, {%8,%9}, {%0,%1,%2,%3};"
        : "+f"(d[0]), "+f"(d[1]), "+f"(d[2]), "+f"(d[3])
        : "r"(a[0]), "r"(a[1]), "r"(a[2]), "r"(a[3]), "r"(b[0]), "r"(b[1]));
}

// ---------------------------------------------------------------------------
// Split-bf16 tensor-core GEMM: C[M,N] = A[M,256] @ B[N,256]^T (+bias).
// Per-CTA tile 128x64, BK=32, 256 threads (8 warps: 2M x 4N, warp tile 64x16).
// In-kernel fp32 -> (hi,lo) bf16 conversion; D = Ah*Bh + Ah*Bl + Al*Bh.
// mode 0: A = Ain (feats), qkv epilogue (route q/k/v + scale q).
// mode 1: A = g_att (device symbol), plain out + bias.
// ---------------------------------------------------------------------------
#define SROW 40   // bf16 row stride (80B): ldmatrix conflict-free

__global__ __launch_bounds__(256) void mma_gemm_kernel(
    const float* __restrict__ Ain, const float* __restrict__ B,
    const float* __restrict__ bias, float* __restrict__ outp, int mode)
{
    __shared__ __align__(16) __nv_bfloat16 sAhi[128 * SROW];
    __shared__ __align__(16) __nv_bfloat16 sAlo[128 * SROW];
    __shared__ __align__(16) __nv_bfloat16 sBhi[64 * SROW];
    __shared__ __align__(16) __nv_bfloat16 sBlo[64 * SROW];

    const float* A = (mode == 1) ? g_att : Ain;   // device-symbol resolution

    const int tid = threadIdx.x, wid = tid >> 5, lane = tid & 31;
    const int m0 = blockIdx.x * 128, n0 = blockIdx.y * 64;
    const int warpM = wid & 1, warpN = wid >> 1;   // 2 x 4 warp grid

    const u32 aHiB = smem_u32(sAhi), aLoB = smem_u32(sAlo);
    const u32 bHiB = smem_u32(sBhi), bLoB = smem_u32(sBlo);

    float acc[4][2][4];   // [mtile][ntile][frag]
#pragma unroll
    for (int mt = 0; mt < 4; mt++)
#pragma unroll
        for (int nt = 0; nt < 2; nt++)
#pragma unroll
            for (int f = 0; f < 4; f++) acc[mt][nt][f] = 0.f;

    // per-lane ldmatrix base offsets
    const u32 aRow = (u32)(warpM * 64 + (lane & 15));
    const u32 aColByte = (u32)((lane >> 4) * 16);          // 8 bf16 half
    const u32 bRowLane = (u32)(lane & 7);
    const u32 bColByte = (u32)(((lane >> 3) & 1) * 16);

    for (int kc = 0; kc < 8; kc++) {
        __syncthreads();
        // ---- load fp32 chunk + convert to hi/lo bf16 in smem ----
        {
            const float* Ap = A + (size_t)m0 * 256 + kc * 32;
#pragma unroll
            for (int it = 0; it < 4; it++) {
                int e = tid + it * 256;          // 1024 float4s
                int row = e >> 3, c4 = e & 7;
                float4 v = *(const float4*)(Ap + (size_t)row * 256 + c4 * 4);
                __nv_bfloat16 h0 = __float2bfloat16(v.x);
                __nv_bfloat16 h1 = __float2bfloat16(v.y);
                __nv_bfloat16 h2 = __float2bfloat16(v.z);
                __nv_bfloat16 h3 = __float2bfloat16(v.w);
                __nv_bfloat162* hp =
                    (__nv_bfloat162*)(sAhi + row * SROW + c4 * 4);
                hp[0] = __halves2bfloat162(h0, h1);
                hp[1] = __halves2bfloat162(h2, h3);
                __nv_bfloat162* lp =
                    (__nv_bfloat162*)(sAlo + row * SROW + c4 * 4);
                lp[0] = __halves2bfloat162(
                    __float2bfloat16(v.x - __bfloat162float(h0)),
                    __float2bfloat16(v.y - __bfloat162float(h1)));
                lp[1] = __halves2bfloat162(
                    __float2bfloat16(v.z - __bfloat162float(h2)),
                    __float2bfloat16(v.w - __bfloat162float(h3)));
            }
            const float* Bp = B + (size_t)n0 * 256 + kc * 32;
#pragma unroll
            for (int it = 0; it < 2; it++) {
                int e = tid + it * 256;          // 512 float4s
                int row = e >> 3, c4 = e & 7;
                float4 v = *(const float4*)(Bp + (size_t)row * 256 + c4 * 4);
                __nv_bfloat16 h0 = __float2bfloat16(v.x);
                __nv_bfloat16 h1 = __float2bfloat16(v.y);
                __nv_bfloat16 h2 = __float2bfloat16(v.z);
                __nv_bfloat16 h3 = __float2bfloat16(v.w);
                __nv_bfloat162* hp =
                    (__nv_bfloat162*)(sBhi + row * SROW + c4 * 4);
                hp[0] = __halves2bfloat162(h0, h1);
                hp[1] = __halves2bfloat162(h2, h3);
                __nv_bfloat162* lp =
                    (__nv_bfloat162*)(sBlo + row * SROW + c4 * 4);
                lp[0] = __halves2bfloat162(
                    __float2bfloat16(v.x - __bfloat162float(h0)),
                    __float2bfloat16(v.y - __bfloat162float(h1)));
                lp[1] = __halves2bfloat162(
                    __float2bfloat16(v.z - __bfloat162float(h2)),
                    __float2bfloat16(v.w - __bfloat162float(h3)));
            }
        }
        __syncthreads();

        // ---- 2 k16 steps of mma ----
#pragma unroll
        for (int s = 0; s < 2; s++) {
            u32 ahi[4][4], alo[4][4], bhi[2][2], blo[2][2];
            const u32 sb = (u32)(s * 32);   // 16 bf16 = 32B
#pragma unroll
            for (int mt = 0; mt < 4; mt++) {
                u32 off = (aRow + mt * 16) * (SROW * 2) + sb + aColByte;
                ldsm4(ahi[mt], aHiB + off);
                ldsm4(alo[mt], aLoB + off);
            }
#pragma unroll
            for (int nt = 0; nt < 2; nt++) {
                u32 off = (u32)(warpN * 16 + nt * 8 + bRowLane) * (SROW * 2)
                          + sb + bColByte;
                ldsm2(bhi[nt], bHiB + off);
                ldsm2(blo[nt], bLoB + off);
            }
#pragma unroll
            for (int mt = 0; mt < 4; mt++)
#pragma unroll
                for (int nt = 0; nt < 2; nt++) {
                    mma_bf16(acc[mt][nt], ahi[mt], bhi[nt]);
                    mma_bf16(acc[mt][nt], ahi[mt], blo[nt]);
                    mma_bf16(acc[mt][nt], alo[mt], bhi[nt]);
                }
        }
    }

    // ---- epilogue ----
    const int mBase = m0 + warpM * 64 + (lane >> 2);
    const int nBase = n0 + warpN * 16 + (lane & 3) * 2;
    if (mode == 0) {
        const int s = nBase >> 8;                 // warp's 16 cols never cross
        float* dst = (s == 0) ? g_q : (s == 1) ? g_k : g_v;
        const float sc = (s == 0) ? QSCALE : 1.0f;
#pragma unroll
        for (int mt = 0; mt < 4; mt++)
#pragma unroll
            for (int nt = 0; nt < 2; nt++) {
                int n = nBase + nt * 8, col = n & 255;
                float b0 = bias[n], b1 = bias[n + 1];
                int mA = mBase + mt * 16, mB = mA + 8;
                float2 oA = {(acc[mt][nt][0] + b0) * sc,
                             (acc[mt][nt][1] + b1) * sc};
                float2 oB = {(acc[mt][nt][2] + b0) * sc,
                             (acc[mt][nt][3] + b1) * sc};
                *(float2*)&dst[(size_t)mA * 256 + col] = oA;
                *(float2*)&dst[(size_t)mB * 256 + col] = oB;
            }
    } else {
#pragma unroll
        for (int mt = 0; mt < 4; mt++)
#pragma unroll
            for (int nt = 0; nt < 2; nt++) {
                int n = nBase + nt * 8;
                float b0 = bias[n], b1 = bias[n + 1];
                int mA = mBase + mt * 16, mB = mA + 8;
                float2 oA = {acc[mt][nt][0] + b0, acc[mt][nt][1] + b1};
                float2 oB = {acc[mt][nt][2] + b0, acc[mt][nt][3] + b1};
                *(float2*)&outp[(size_t)mA * 256 + n] = oA;
                *(float2*)&outp[(size_t)mB * 256 + n] = oB;
            }
    }
}

// ---------------------------------------------------------------------------
// Attention kernel: EXACT R7 version (best measured, 512 threads).
// ---------------------------------------------------------------------------
#define SM_FLOATS 53024
#define SMEM_BYTES (SM_FLOATS * 4)

__global__ __launch_bounds__(512) void attn_kernel(
    const float* __restrict__ n_coords,
    const float* __restrict__ qx, const float* __restrict__ kx,
    const float* __restrict__ vx,
    const float* __restrict__ qr, const float* __restrict__ kr,
    const float* __restrict__ vr)
{
    extern __shared__ __align__(16) float sm[];
    float* scw   = sm;
    float* sq    = sm + 384;     // stride 33
    float* sk    = sm + 2496;    // stride 33
    float* svT   = sm + 4608;    // stride 65
    float* stabQ = sm + 6688;
    float* stabK = sm + 13600;
    float* sdq   = sm + 20512;   // stride 220
    float* sdk   = sm + 34592;   // stride 220
    float* slogT = sm + 48672;   // stride 68, [j][i]
    float* satT  = sm + 20512;   // stride 68, [t][i]   (aliases sdq after logits)
    float* vtabT = sm + 35200;   // stride 217, [d][t]  (aliases sdk tail)
    u64*   s_idx = (u64*)(sm + 6688);   // u64[4096] over stabQ/K (after Dq/Dk)

    const int nb = blockIdx.x, h = blockIdx.y;
    const int tid = threadIdx.x;
    const int l = tid & 31, w = tid >> 5;
    const int tok0 = nb * WW;

    for (int s = tid; s < WW * 6; s += 512) {
        int i = s / 6, c = s % 6;
        scw[s] = n_coords[(tok0 + i) * 6 + c] * (c < 3 ? 4.0f : 8.0f);
    }
    for (int s = tid; s < WW * HD; s += 512) {
        int i = s >> 5, d = s & 31;
        int g = (tok0 + i) * 256 + h * 32 + d;
        sq[i * 33 + d]  = g_q[g];
        sk[i * 33 + d]  = g_k[g];
        svT[d * 65 + i] = g_v[g];
    }
    for (int s = tid; s < T6 * HD; s += 512) {
        int t = s >> 5, d = s & 31;
        stabQ[s] = (t < 120) ? qx[(t * 8 + h) * 32 + d]
                             : qr[((t - 120) * 8 + h) * 32 + d];
        stabK[s] = (t < 120) ? kx[(t * 8 + h) * 32 + d]
                             : kr[((t - 120) * 8 + h) * 32 + d];
    }
    __syncthreads();

    {
        const int i = tid & 63, grp = tid >> 6;
        const int t0 = grp * 27, t1 = t0 + 27;
        u64 a2[16];
#pragma unroll
        for (int d2 = 0; d2 < 16; d2++)
            a2[d2] = pk2(sq[i * 33 + 2 * d2], sq[i * 33 + 2 * d2 + 1]);
        for (int t = t0; t < t1; t++) {
            const ulonglong2* tv = (const ulonglong2*)(stabQ + t * 32);
            u64 acc = pk2(0.f, 0.f);
#pragma unroll
            for (int d4 = 0; d4 < 8; d4++) {
                ulonglong2 tvv = tv[d4];
                ffma2(acc, a2[2 * d4],     tvv.x);
                ffma2(acc, a2[2 * d4 + 1], tvv.y);
            }
            sdq[i * 220 + t] = hsum2(acc);
        }
#pragma unroll
        for (int d2 = 0; d2 < 16; d2++)
            a2[d2] = pk2(sk[i * 33 + 2 * d2], sk[i * 33 + 2 * d2 + 1]);
        for (int t = t0; t < t1; t++) {
            const ulonglong2* tv = (const ulonglong2*)(stabK + t * 32);
            u64 acc = pk2(0.f, 0.f);
#pragma unroll
            for (int d4 = 0; d4 < 8; d4++) {
                ulonglong2 tvv = tv[d4];
                ffma2(acc, a2[2 * d4],     tvv.x);
                ffma2(acc, a2[2 * d4 + 1], tvv.y);
            }
            sdk[i * 220 + t] = hsum2(acc);
        }
    }
    __syncthreads();

    {
        const int basec[6] = {0, 40, 80, 120, 152, 184};
        const int offc[6]  = {20, 20, 20, 16, 16, 16};
        const int hic[6]   = {39, 39, 39, 31, 31, 31};
#pragma unroll
        for (int r = 0; r < 4; r++) {
            int i = w * 4 + r;
            float ci[6];
#pragma unroll
            for (int c = 0; c < 6; c++) ci[c] = scw[i * 6 + c];
            u64 q2[16];
#pragma unroll
            for (int d2 = 0; d2 < 16; d2++)
                q2[d2] = pk2(sq[i * 33 + 2 * d2], sq[i * 33 + 2 * d2 + 1]);
#pragma unroll
            for (int jj = 0; jj < 2; jj++) {
                int j = l + jj * 32;
                const float* krow = sk + j * 33;
                u64 acc2 = pk2(0.f, 0.f);
#pragma unroll
                for (int d2 = 0; d2 < 16; d2++)
                    ffma2(acc2, q2[d2], pk2(krow[2 * d2], krow[2 * d2 + 1]));
                float acc = hsum2(acc2);
                u64 pack = 0;
#pragma unroll
                for (int c = 0; c < 6; c++) {
                    int id = (int)floorf(ci[c] - scw[j * 6 + c]) + offc[c];
                    id = min(max(id, 0), hic[c]);
                    int t = basec[c] + id;
                    acc += sdq[i * 220 + t] + sdk[j * 220 + t];
                    pack |= (u64)t << (8 * c);
                }
                slogT[j * 68 + i] = acc;
                s_idx[i * 64 + j] = pack;
            }
        }
    }
    __syncthreads();

    for (int s = tid; s < T6 * 68; s += 512) satT[s] = 0.f;
    for (int s = tid; s < T6 * HD; s += 512) {
        int t = s >> 5, d = s & 31;
        float val = (t < 120) ? vx[(t * 8 + h) * 32 + d]
                              : vr[((t - 120) * 8 + h) * 32 + d];
        vtabT[d * 217 + t] = val;
    }
    __syncthreads();

#pragma unroll
    for (int r = 0; r < 4; r++) {
        int i = w * 4 + r;
        float v0 = slogT[l * 68 + i], v1 = slogT[(l + 32) * 68 + i];
        float m = fmaxf(v0, v1);
#pragma unroll
        for (int o = 16; o > 0; o >>= 1)
            m = fmaxf(m, __shfl_xor_sync(0xffffffffu, m, o));
        float e0 = __expf(v0 - m), e1 = __expf(v1 - m);
        float s = e0 + e1;
#pragma unroll
        for (int o = 16; o > 0; o >>= 1)
            s += __shfl_xor_sync(0xffffffffu, s, o);
        float inv = 1.0f / s;
        slogT[l * 68 + i]        = e0 * inv;
        slogT[(l + 32) * 68 + i] = e1 * inv;
    }
    __syncwarp();

    if (l < 24) {
        int r = l / 6, c = l % 6;
        int i = w * 4 + r;
        const u64* ip = s_idx + i * 64;
        const int sh = 8 * c;
        for (int j = 0; j < 64; j++) {
            int t = (int)((ip[j] >> sh) & 255u);
            satT[t * 68 + i] += slogT[j * 68 + i];
        }
    }
    __syncwarp();

    {
        const int i0 = w * 4;
        u64 acc01 = pk2(0.f, 0.f), acc23 = pk2(0.f, 0.f);
        const float* svrow = svT + l * 65;
#pragma unroll 8
        for (int j = 0; j < 64; j++) {
            float4 a4 = *(const float4*)&slogT[j * 68 + i0];
            float v = svrow[j];
            u64 vd = pk2(v, v);
            ffma2(acc01, pk2(a4.x, a4.y), vd);
            ffma2(acc23, pk2(a4.z, a4.w), vd);
        }
        const float* vtrow = vtabT + l * 217;
#pragma unroll 8
        for (int t = 0; t < T6; t++) {
            float4 a4 = *(const float4*)&satT[t * 68 + i0];
            float v = vtrow[t];
            u64 vd = pk2(v, v);
            ffma2(acc01, pk2(a4.x, a4.y), vd);
            ffma2(acc23, pk2(a4.z, a4.w), vd);
        }
        float2 o01 = up2(acc01), o23 = up2(acc23);
        const int ob = (tok0 + i0) * 256 + h * 32 + l;
        g_att[ob]       = o01.x;
        g_att[ob + 256] = o01.y;
        g_att[ob + 512] = o23.x;
        g_att[ob + 768] = o23.y;
    }
}

// ---------------------------------------------------------------------------
extern "C" void kernel_launch(void* const* d_in, const int* in_sizes, int n_in,
                              void* d_out, int out_size)
{
    const float* feats    = (const float*)d_in[0];
    const float* n_coords = (const float*)d_in[1];
    const float* qkv_w    = (const float*)d_in[2];
    const float* qkv_b    = (const float*)d_in[3];
    const float* qx       = (const float*)d_in[4];
    const float* kx       = (const float*)d_in[5];
    const float* vx       = (const float*)d_in[6];
    const float* qr       = (const float*)d_in[7];
    const float* kr       = (const float*)d_in[8];
    const float* vr       = (const float*)d_in[9];
    const float* pw       = (const float*)d_in[10];
    const float* pb       = (const float*)d_in[11];
    float* out = (float*)d_out;

    cudaFuncSetAttribute(attn_kernel,
                         cudaFuncAttributeMaxDynamicSharedMemorySize,
                         SMEM_BYTES);

    // qkv: [8192,768] = feats @ qkv_w^T  (mma.sync split-bf16)
    mma_gemm_kernel<<<dim3(64, 12), 256>>>(feats, qkv_w, qkv_b, nullptr, 0);

    attn_kernel<<<dim3(NW, HH), 512, SMEM_BYTES>>>(n_coords, qx, kx, vx,
                                                   qr, kr, vr);

    // proj: [8192,256] = g_att @ proj_w^T  (A resolved to g_att in-kernel)
    mma_gemm_kernel<<<dim3(64, 4), 256>>>(nullptr, pw, pb, out, 1);
}